// round 12
// baseline (speedup 1.0000x reference)
#include <cuda_runtime.h>
#include <math.h>
#include <stdint.h>

#define NB 131072
#define DD 1024
#define HH 128

// Scratch (allocation-free rule: __device__ globals)
__device__ float g_W1t[HH * DD];   // W1[:1024]^T as tf32 bits [N=128][K=1024]
__device__ float g_W2p[HH * HH];   // W2^T tf32 bits, fragment-paired: see prep
__device__ float g_part[2048 * 2]; // per-block (loss_sum, n_masked) partials

__constant__ int c_perms[6][3] = {
  {0,1,2},{0,2,1},{1,0,2},{1,2,0},{2,0,1},{2,1,0}
};

__device__ __forceinline__ float gelu_f(float x){
  return 0.5f * x * (1.0f + erff(x * 0.7071067811865476f));
}

// ---------------------------------------------------------------------------
// PTX helpers (baseline sm_100: cp.async + mma.sync tf32)
// ---------------------------------------------------------------------------
__device__ __forceinline__ void cp_async16(uint32_t dst, const void* src){
  asm volatile("cp.async.cg.shared.global [%0], [%1], 16;" :: "r"(dst), "l"(src) : "memory");
}
__device__ __forceinline__ void cp_commit(){
  asm volatile("cp.async.commit_group;" ::: "memory");
}
__device__ __forceinline__ uint32_t smem_u32(const void* p){
  uint32_t a;
  asm("{ .reg .u64 t; cvta.to.shared.u64 t, %1; cvt.u32.u64 %0, t; }" : "=r"(a) : "l"(p));
  return a;
}
__device__ __forceinline__ uint32_t f2tf(float x){
  uint32_t r;
  asm("cvt.rna.tf32.f32 %0, %1;" : "=r"(r) : "f"(x));
  return r;
}
__device__ __forceinline__ void mma_tf32(float* c, const uint32_t* a, const uint32_t* b){
  asm volatile(
    "mma.sync.aligned.m16n8k8.row.col.f32.tf32.tf32.f32 "
    "{%0,%1,%2,%3}, {%4,%5,%6,%7}, {%8,%9}, {%0,%1,%2,%3};"
    : "+f"(c[0]), "+f"(c[1]), "+f"(c[2]), "+f"(c[3])
    : "r"(a[0]), "r"(a[1]), "r"(a[2]), "r"(a[3]), "r"(b[0]), "r"(b[1]));
}

// ---------------------------------------------------------------------------
// Kernel T: W1^T -> g_W1t (tf32 bits); W2 -> g_W2p (tf32 bits, paired):
// pair p(n,kk,tg) = { W2t[n][kk*8+tg], W2t[n][kk*8+tg+4] } at float2 idx
// n*64 + kk*4 + tg  (W2t[n][k] = W2[k][n]).
// ---------------------------------------------------------------------------
__global__ void __launch_bounds__(256) prep_weights(
    const float* __restrict__ W1, const float* __restrict__ W2)
{
  int i = blockIdx.x * 256 + threadIdx.x;          // 0 .. 147455
  if (i < 131072){
    int k = i >> 7, n = i & 127;
    g_W1t[(size_t)n * DD + k] = __uint_as_float(f2tf(W1[(size_t)k * HH + n]));
  } else {
    int j = i - 131072;                            // 0 .. 16383
    int k = j >> 7, n = j & 127;                   // W2 row k, col n
    int kk = k >> 3, t = k & 7;
    int fidx = ((n*64 + kk*4 + (t & 3)) << 1) | (t >> 2);
    g_W2p[fidx] = __uint_as_float(f2tf(W2[k * HH + n]));
  }
}

// ---------------------------------------------------------------------------
// Fused kernel: CTA = 64 rows, 128 threads (4 warps), 2 CTAs/SM.
// Phase 1 (gemm): 64x128 tile, warp tile 32x64, K=1024, 2-stage cp.async ring.
//                 Epilogue writes base = Y0 + b1 into smem.
// Phase 2 (steps): R10 decoder body; W2 fragments via __ldg from L1
//                  (shared across both resident CTAs).
// smem floats (25160 total = 100,640 B):
//   [0,8448)        base [64][132]
//   [8448,22272)    gemm stages 2 x (A 64x36 + B 128x36)  | h1 [64][132] after
//   [22272,23808)   W1e [12][128]
//   [23808,24064)   W3p [128][2]
//   [24064,24192)   b2s
//   [24192,24320)   b1s
//   [24320,25088)   st [64][12]
//   [25088,25152)   sridx (int)
//   [25152,25160)   wred
// ---------------------------------------------------------------------------
#define RSA 36
#define A_STG (64 * RSA)            // 2304
#define B_STG (128 * RSA)           // 4608
#define STG_TOT (A_STG + B_STG)     // 6912
#define RS2 132
#define OFF_BASE  0
#define OFF_STAGE 8448
#define OFF_H1    8448
#define OFF_W1E   22272
#define OFF_W3P   23808
#define OFF_B2S   24064
#define OFF_B1S   24192
#define OFF_ST    24320
#define OFF_RIDX  25088
#define OFF_WRED  25152
#define SMEM_F_BYTES (25160 * 4)    // 100640 -> 2 CTAs/SM

__global__ void __launch_bounds__(128, 2) fused_kernel(
    const float* __restrict__ A,
    const float* __restrict__ freq, const float* __restrict__ pres,
    const float* __restrict__ rmask, const int* __restrict__ perm_idx,
    const float* __restrict__ W1,  const float* __restrict__ b1,
    const float* __restrict__ b2,
    const float* __restrict__ W3,  const float* __restrict__ b3,
    float* __restrict__ out)
{
  extern __shared__ float smf[];
  const uint32_t sbase = smem_u32(smf);
  float* basep = smf + OFF_BASE;
  float* h1    = smf + OFF_H1;
  float* W1e   = smf + OFF_W1E;
  float* W3p   = smf + OFF_W3P;
  float* b2s   = smf + OFF_B2S;
  float* b1s   = smf + OFF_B1S;
  float* st    = smf + OFF_ST;
  int*   sridx = (int*)(smf + OFF_RIDX);
  float* wred  = smf + OFF_WRED;

  const int tid  = threadIdx.x;
  const int wid  = tid >> 5, lane = tid & 31;
  const int gr   = lane >> 2, tg = lane & 3;
  const int row0 = blockIdx.x * 64;

  // ---- small statics (outside stage region) ----
  for (int i = tid; i < 384; i += 128)
    *(float4*)&W1e[i*4] = *(const float4*)&W1[1024*HH + i*4];
  for (int i = tid; i < 64; i += 128)
    *(float4*)&W3p[i*4] = *(const float4*)&W3[i*4];
  b2s[tid] = b2[tid];
  b1s[tid] = b1[tid];
  for (int i = tid; i < 768; i += 128) st[i] = 0.f;

  // ============================ GEMM PHASE =================================
  {
    const int wm = (wid & 1) * 32;     // warp M offset
    const int wn = (wid >> 1) * 64;    // warp N offset
    const float* Abase = A + (size_t)row0 * DD;

    auto load_stage = [&](int s){
      const int buf = s & 1;
      const int k0  = s * 32;
      const uint32_t aB = sbase + (uint32_t)(OFF_STAGE + buf * STG_TOT) * 4u;
      const uint32_t bB = aB + (uint32_t)A_STG * 4u;
#pragma unroll
      for (int j = 0; j < 4; j++){                 // A: 64 rows x 8 chunks
        int idx = tid + 128*j;
        int row = idx >> 3, cc = idx & 7;
        cp_async16(aB + (uint32_t)(row*RSA + cc*4)*4u,
                   Abase + (size_t)row*DD + k0 + cc*4);
      }
#pragma unroll
      for (int j = 0; j < 8; j++){                 // B: 128 rows x 8 chunks
        int idx = tid + 128*j;
        int row = idx >> 3, cc = idx & 7;
        cp_async16(bB + (uint32_t)(row*RSA + cc*4)*4u,
                   g_W1t + (size_t)row*DD + k0 + cc*4);
      }
      cp_commit();
    };

    float acc[2][8][4];
#pragma unroll
    for (int mt = 0; mt < 2; mt++)
#pragma unroll
      for (int nt = 0; nt < 8; nt++)
#pragma unroll
        for (int i = 0; i < 4; i++) acc[mt][nt][i] = 0.f;

    load_stage(0);
    load_stage(1);

    for (int s = 0; s < 32; s++){
      if (s < 31) asm volatile("cp.async.wait_group 1;" ::: "memory");
      else        asm volatile("cp.async.wait_group 0;" ::: "memory");
      __syncthreads();

      const float* Abuf = smf + OFF_STAGE + (s & 1) * STG_TOT;
      const float* Bbuf = Abuf + A_STG;

#pragma unroll
      for (int kk = 0; kk < 4; kk++){
        const int kc = kk * 8;
        uint32_t af[2][4], bf[8][2];
#pragma unroll
        for (int mt = 0; mt < 2; mt++){
          int r = wm + mt*16 + gr;
          af[mt][0] = f2tf(Abuf[r*RSA + kc + tg]);
          af[mt][1] = f2tf(Abuf[(r+8)*RSA + kc + tg]);
          af[mt][2] = f2tf(Abuf[r*RSA + kc + tg + 4]);
          af[mt][3] = f2tf(Abuf[(r+8)*RSA + kc + tg + 4]);
        }
#pragma unroll
        for (int nt = 0; nt < 8; nt++){
          int n = wn + nt*8 + gr;
          bf[nt][0] = __float_as_uint(Bbuf[n*RSA + kc + tg]);   // pre-rounded tf32
          bf[nt][1] = __float_as_uint(Bbuf[n*RSA + kc + tg + 4]);
        }
#pragma unroll
        for (int mt = 0; mt < 2; mt++)
#pragma unroll
          for (int nt = 0; nt < 8; nt++)
            mma_tf32(acc[mt][nt], af[mt], bf[nt]);
      }
      __syncthreads();                 // all warps done reading buf (s&1)
      if (s + 2 < 32) load_stage(s + 2);
    }

    // epilogue: base = acc + b1 (smem)
#pragma unroll
    for (int mt = 0; mt < 2; mt++){
#pragma unroll
      for (int nt = 0; nt < 8; nt++){
        int r   = wm + mt*16 + gr;
        int col = wn + nt*8 + 2*tg;
        float bb0 = b1s[col], bb1 = b1s[col+1];
        float2 lo = { acc[mt][nt][0] + bb0, acc[mt][nt][1] + bb1 };
        float2 hi = { acc[mt][nt][2] + bb0, acc[mt][nt][3] + bb1 };
        *(float2*)&basep[r*RS2 + col]     = lo;
        *(float2*)&basep[(r+8)*RS2 + col] = hi;
      }
    }
  }
  __syncthreads();

  // ============================ STEPS PHASE ================================
  const int wm = wid * 16;
  const float b30 = b3[0], b31 = b3[1];
  const float2* W2p = reinterpret_cast<const float2*>(g_W2p);

  int p_lo = 0, p_hi = 0;
  if (tg == 0){
    p_lo = perm_idx[row0 + wm + gr];
    p_hi = perm_idx[row0 + wm + gr + 8];
  }

  float lsum = 0.f, msum = 0.f;

  for (int step = 0; step < 3; step++){
    // (a) tail lanes publish ridx + fetch ground truth
    float gtf_lo=0, gtp_lo=0, m_lo=0, gtf_hi=0, gtp_hi=0, m_hi=0;
    int r_lo=0, r_hi=0;
    if (tg == 0){
      r_lo = c_perms[p_lo][step]; r_hi = c_perms[p_hi][step];
      sridx[wm+gr]   = r_lo;
      sridx[wm+gr+8] = r_hi;
      size_t qlo = (size_t)(row0+wm+gr)*3 + r_lo;
      size_t qhi = (size_t)(row0+wm+gr+8)*3 + r_hi;
      gtf_lo = freq[qlo]; gtp_lo = pres[qlo]; m_lo = rmask[qlo];
      gtf_hi = freq[qhi]; gtp_hi = pres[qhi]; m_hi = rmask[qhi];
    }
    __syncthreads();

    // (b) layer 1: h1 = gelu(base + state@W1e + onehot_row)
#pragma unroll
    for (int r = 0; r < 16; r++){
      float4 acc = *(float4*)&basep[(wm+r)*RS2 + lane*4];
      int ri = sridx[wm+r];
      if (step > 0){
#pragma unroll
        for (int i = 0; i < 9; i++){
          float s = st[(wm+r)*12 + i];
          float4 w = *(float4*)&W1e[i*HH + lane*4];
          acc.x = fmaf(s, w.x, acc.x); acc.y = fmaf(s, w.y, acc.y);
          acc.z = fmaf(s, w.z, acc.z); acc.w = fmaf(s, w.w, acc.w);
        }
      }
      float4 w = *(float4*)&W1e[(9+ri)*HH + lane*4];
      acc.x = gelu_f(acc.x + w.x); acc.y = gelu_f(acc.y + w.y);
      acc.z = gelu_f(acc.z + w.z); acc.w = gelu_f(acc.w + w.w);
      *(float4*)&h1[(wm+r)*RS2 + lane*4] = acc;
    }
    __syncthreads();

    // (c) layer 2: warp tile 16x128 mma, K=128; W2 frags via L1 (__ldg)
    float acc[16][4];
#pragma unroll
    for (int nt = 0; nt < 16; nt++)
#pragma unroll
      for (int i = 0; i < 4; i++) acc[nt][i] = 0.f;

#pragma unroll
    for (int kk = 0; kk < 16; kk++){
      const int kc = kk * 8;
      uint32_t af[4];
      af[0] = f2tf(h1[(wm+gr)*RS2   + kc + tg]);
      af[1] = f2tf(h1[(wm+gr+8)*RS2 + kc + tg]);
      af[2] = f2tf(h1[(wm+gr)*RS2   + kc + tg + 4]);
      af[3] = f2tf(h1[(wm+gr+8)*RS2 + kc + tg + 4]);
#pragma unroll
      for (int nt = 0; nt < 16; nt++){
        float2 v = __ldg(&W2p[(nt*8+gr)*64 + kk*4 + tg]);
        uint32_t bf[2] = { __float_as_uint(v.x), __float_as_uint(v.y) };
        mma_tf32(acc[nt], af, bf);
      }
    }

    // (d) gelu + W3 projection on fragments
    float pf_lo = 0.f, z_lo = 0.f, pf_hi = 0.f, z_hi = 0.f;
#pragma unroll
    for (int nt = 0; nt < 16; nt++){
      int c0 = nt*8 + 2*tg;
      float bb0 = b2s[c0], bb1 = b2s[c0+1];
      float g0 = gelu_f(acc[nt][0] + bb0);
      float g1 = gelu_f(acc[nt][1] + bb1);
      float g2 = gelu_f(acc[nt][2] + bb0);
      float g3 = gelu_f(acc[nt][3] + bb1);
      float2 wA = *(float2*)&W3p[c0*2];
      float2 wB = *(float2*)&W3p[(c0+1)*2];
      pf_lo = fmaf(g0, wA.x, fmaf(g1, wB.x, pf_lo));
      z_lo  = fmaf(g0, wA.y, fmaf(g1, wB.y, z_lo));
      pf_hi = fmaf(g2, wA.x, fmaf(g3, wB.x, pf_hi));
      z_hi  = fmaf(g2, wA.y, fmaf(g3, wB.y, z_hi));
    }
#pragma unroll
    for (int o = 1; o <= 2; o <<= 1){
      pf_lo += __shfl_xor_sync(0xffffffffu, pf_lo, o);
      z_lo  += __shfl_xor_sync(0xffffffffu, z_lo,  o);
      pf_hi += __shfl_xor_sync(0xffffffffu, pf_hi, o);
      z_hi  += __shfl_xor_sync(0xffffffffu, z_hi,  o);
    }

    // (e) per-row tail on tg==0 lanes (2 rows each)
    if (tg == 0){
#pragma unroll
      for (int hh = 0; hh < 2; hh++){
        int   row  = wm + gr + hh*8;
        float pf   = (hh ? pf_hi : pf_lo) + b30;
        float z    = (hh ? z_hi  : z_lo)  + b31;
        float gtf  = hh ? gtf_hi : gtf_lo;
        float gtp  = hh ? gtp_hi : gtp_lo;
        float m    = hh ? m_hi   : m_lo;
        int   ri   = hh ? r_hi   : r_lo;
        float d  = pf - gtf;
        float pl = (fmaxf(z, 0.f) - z*gtp + log1pf(expf(-fabsf(z)))) * m;
        lsum += d*d*m + pl;
        msum += m;
        float sig   = 1.f / (1.f + expf(-z));
        float act_f = (m > 0.5f) ? pf  : gtf;
        float act_p = (m > 0.5f) ? sig : gtp;
        st[row*12 + 3*ri + 0] = act_f;
        st[row*12 + 3*ri + 1] = act_p;
        st[row*12 + 3*ri + 2] = 1.f;
        size_t rowr = (size_t)(row0 + row);
        out[1 + rowr*3 + ri]                = act_f;
        out[1 + (size_t)3*NB + rowr*3 + ri] = act_p;
      }
    }
    __syncthreads();
  }

  // block loss reduction (deterministic)
#pragma unroll
  for (int o = 16; o; o >>= 1){
    lsum += __shfl_xor_sync(0xffffffffu, lsum, o);
    msum += __shfl_xor_sync(0xffffffffu, msum, o);
  }
  if (lane == 0){ wred[wid*2] = lsum; wred[wid*2+1] = msum; }
  __syncthreads();
  if (tid == 0){
    float L = 0.f, M = 0.f;
#pragma unroll
    for (int w = 0; w < 4; w++){ L += wred[w*2]; M += wred[w*2+1]; }
    g_part[blockIdx.x*2]   = L;
    g_part[blockIdx.x*2+1] = M;
  }
}

// ---------------------------------------------------------------------------
// Kernel C: deterministic final reduction -> out[0]
// ---------------------------------------------------------------------------
__global__ void __launch_bounds__(256) finalize_kernel(float* __restrict__ out)
{
  __shared__ float sL[256], sM[256];
  int tid = threadIdx.x;
  float L = 0.f, M = 0.f;
  for (int i = tid; i < 2048; i += 256){ L += g_part[2*i]; M += g_part[2*i+1]; }
  sL[tid] = L; sM[tid] = M;
  __syncthreads();
  for (int s = 128; s; s >>= 1){
    if (tid < s){ sL[tid] += sL[tid+s]; sM[tid] += sM[tid+s]; }
    __syncthreads();
  }
  if (tid == 0) out[0] = sL[0] / (sM[0] + 1e-8f);
}

// ---------------------------------------------------------------------------
extern "C" void kernel_launch(void* const* d_in, const int* in_sizes, int n_in,
                              void* d_out, int out_size)
{
  const float* seq   = (const float*)d_in[0];
  const float* freq  = (const float*)d_in[1];
  const float* pres  = (const float*)d_in[2];
  const float* rmask = (const float*)d_in[3];
  const int*   perm  = (const int*)  d_in[4];
  const float* W1    = (const float*)d_in[5];
  const float* b1    = (const float*)d_in[6];
  const float* W2    = (const float*)d_in[7];
  const float* b2    = (const float*)d_in[8];
  const float* W3    = (const float*)d_in[9];
  const float* b3    = (const float*)d_in[10];
  float* out = (float*)d_out;

  cudaFuncSetAttribute(fused_kernel,
                       cudaFuncAttributeMaxDynamicSharedMemorySize, SMEM_F_BYTES);

  prep_weights<<<576, 256>>>(W1, W2);
  fused_kernel<<<NB/64, 128, SMEM_F_BYTES>>>(seq, freq, pres, rmask, perm,
                                             W1, b1, b2, W3, b3, out);
  finalize_kernel<<<1, 256>>>(out);
}

// round 14
// speedup vs baseline: 1.2298x; 1.2298x over previous
#include <cuda_runtime.h>
#include <math.h>
#include <stdint.h>

#define NB 131072
#define DD 1024
#define HH 128

// Scratch (allocation-free rule: __device__ globals)
__device__ float g_Y0[(size_t)NB * HH];    // 67 MB: seq_embed @ W1[:1024]
__device__ float g_W1t[HH * DD];           // W1[:1024]^T as tf32 bits [N=128][K=1024]
__device__ float g_W2t[HH * HH];           // W2^T as tf32 bits [N=128][K=128]
__device__ float g_part[2048 * 2];         // per-block (loss_sum, n_masked) partials

__constant__ int c_perms[6][3] = {
  {0,1,2},{0,2,1},{1,0,2},{1,2,0},{2,0,1},{2,1,0}
};

// Fast gelu: Abramowitz-Stegun 7.1.26 erf (|abs err| <= 1.5e-7).
// ~8 FMA-pipe ops + 2 MUFU (rcp.approx, ex2) vs ~25 FMA for erff.
__device__ __forceinline__ float gelu_f(float x){
  float az = fabsf(x) * 0.7071067811865476f;       // z = |x|/sqrt(2)
  float d  = fmaf(0.3275911f, az, 1.0f);
  float t;
  asm("rcp.approx.f32 %0, %1;" : "=f"(t) : "f"(d));
  float y = t * fmaf(t, fmaf(t, fmaf(t, fmaf(t, 1.061405429f, -1.453152027f),
                                     1.421413741f), -0.284496736f), 0.254829592f);
  float e = __expf(-az * az);
  float erfv = fmaf(-y, e, 1.0f);                  // erf(|x|/sqrt(2))
  float s = copysignf(erfv, x);
  return 0.5f * x * (1.0f + s);
}

// ---------------------------------------------------------------------------
// PTX helpers (baseline sm_100: cp.async + mma.sync tf32)
// ---------------------------------------------------------------------------
__device__ __forceinline__ void cp_async16(uint32_t dst, const void* src){
  asm volatile("cp.async.cg.shared.global [%0], [%1], 16;" :: "r"(dst), "l"(src) : "memory");
}
__device__ __forceinline__ void cp_commit(){
  asm volatile("cp.async.commit_group;" ::: "memory");
}
__device__ __forceinline__ uint32_t smem_u32(const void* p){
  uint32_t a;
  asm("{ .reg .u64 t; cvta.to.shared.u64 t, %1; cvt.u32.u64 %0, t; }" : "=r"(a) : "l"(p));
  return a;
}
__device__ __forceinline__ uint32_t f2tf(float x){
  uint32_t r;
  asm("cvt.rna.tf32.f32 %0, %1;" : "=r"(r) : "f"(x));
  return r;
}
__device__ __forceinline__ void mma_tf32(float* c, const uint32_t* a, const uint32_t* b){
  asm volatile(
    "mma.sync.aligned.m16n8k8.row.col.f32.tf32.tf32.f32 "
    "{%0,%1,%2,%3}, {%4,%5,%6,%7}, {%8,%9}, {%0,%1,%2,%3};"
    : "+f"(c[0]), "+f"(c[1]), "+f"(c[2]), "+f"(c[3])
    : "r"(a[0]), "r"(a[1]), "r"(a[2]), "r"(a[3]), "r"(b[0]), "r"(b[1]));
}

// ---------------------------------------------------------------------------
// Kernel T: W1[:1024,128] -> g_W1t (tf32 bits) ; W2 -> g_W2t (tf32 bits)
// ---------------------------------------------------------------------------
__global__ void __launch_bounds__(256) prep_weights(
    const float* __restrict__ W1, const float* __restrict__ W2)
{
  int i = blockIdx.x * 256 + threadIdx.x;          // 0 .. 147455
  if (i < 131072){
    int k = i >> 7, n = i & 127;
    g_W1t[(size_t)n * DD + k] = __uint_as_float(f2tf(W1[(size_t)k * HH + n]));
  } else {
    int j = i - 131072;
    int k = j >> 7, n = j & 127;
    g_W2t[n * HH + k] = __uint_as_float(f2tf(W2[k * HH + n]));
  }
}

// ---------------------------------------------------------------------------
// Kernel A: mma.sync tf32 GEMM (R9/R10 proven).
// CTA 128x128, 4 warps (2x2), warp tile 64x64, K chunk 32, 3-stage cp.async.
// ---------------------------------------------------------------------------
#define RS 36
#define STG_FLOATS (128 * RS)      // 4608
#define SMEM_G_BYTES (3 * 2 * STG_FLOATS * 4)   // 110592 -> 2 CTAs/SM

__global__ void __launch_bounds__(128, 2) tc_gemm(const float* __restrict__ A)
{
  extern __shared__ float sm[];
  const uint32_t sbase = smem_u32(sm);
  const int tid  = threadIdx.x;
  const int wid  = tid >> 5, lane = tid & 31;
  const int gr   = lane >> 2, tg = lane & 3;
  const int m0   = blockIdx.x * 128;
  const int wm   = (wid & 1) * 64;
  const int wn   = (wid >> 1) * 64;

  const float* Abase = A + (size_t)m0 * DD;

  auto load_stage = [&](int s){
    const int buf = s % 3;
    const int k0  = s * 32;
    const uint32_t aB = sbase + (uint32_t)(buf * 2 * STG_FLOATS) * 4u;
    const uint32_t bB = aB + (uint32_t)STG_FLOATS * 4u;
#pragma unroll
    for (int j = 0; j < 8; j++){
      int idx = tid + 128*j;
      int row = idx >> 3, cc = idx & 7;
      uint32_t off = (uint32_t)(row * RS + cc * 4) * 4u;
      cp_async16(aB + off, Abase + (size_t)row * DD + k0 + cc*4);
      cp_async16(bB + off, g_W1t + (size_t)row * DD + k0 + cc*4);
    }
    cp_commit();
  };

  float acc[4][8][4];
#pragma unroll
  for (int mt = 0; mt < 4; mt++)
#pragma unroll
    for (int nt = 0; nt < 8; nt++)
#pragma unroll
      for (int i = 0; i < 4; i++) acc[mt][nt][i] = 0.f;

  load_stage(0);
  load_stage(1);

  for (int s = 0; s < 32; s++){
    if (s < 31) asm volatile("cp.async.wait_group 1;" ::: "memory");
    else        asm volatile("cp.async.wait_group 0;" ::: "memory");
    __syncthreads();
    if (s + 2 < 32) load_stage(s + 2);

    const float* Abuf = sm + (s % 3) * 2 * STG_FLOATS;
    const float* Bbuf = Abuf + STG_FLOATS;

#pragma unroll
    for (int kk = 0; kk < 4; kk++){
      const int kc = kk * 8;
      uint32_t af[4][4], bf[8][2];
#pragma unroll
      for (int mt = 0; mt < 4; mt++){
        int r = wm + mt*16 + gr;
        af[mt][0] = f2tf(Abuf[r*RS + kc + tg]);
        af[mt][1] = f2tf(Abuf[(r+8)*RS + kc + tg]);
        af[mt][2] = f2tf(Abuf[r*RS + kc + tg + 4]);
        af[mt][3] = f2tf(Abuf[(r+8)*RS + kc + tg + 4]);
      }
#pragma unroll
      for (int nt = 0; nt < 8; nt++){
        int n = wn + nt*8 + gr;
        bf[nt][0] = __float_as_uint(Bbuf[n*RS + kc + tg]);
        bf[nt][1] = __float_as_uint(Bbuf[n*RS + kc + tg + 4]);
      }
#pragma unroll
      for (int mt = 0; mt < 4; mt++)
#pragma unroll
        for (int nt = 0; nt < 8; nt++)
          mma_tf32(acc[mt][nt], af[mt], bf[nt]);
    }
  }

#pragma unroll
  for (int mt = 0; mt < 4; mt++){
#pragma unroll
    for (int nt = 0; nt < 8; nt++){
      int row = m0 + wm + mt*16 + gr;
      int col = wn + nt*8 + 2*tg;
      float2 lo = { acc[mt][nt][0], acc[mt][nt][1] };
      float2 hi = { acc[mt][nt][2], acc[mt][nt][3] };
      *(float2*)&g_Y0[(size_t)row*HH + col]       = lo;
      *(float2*)&g_Y0[(size_t)(row+8)*HH + col]   = hi;
    }
  }
}

// ---------------------------------------------------------------------------
// Kernel B: fused 3-step decoder (R10 proven): CTA = 64 rows, 128 threads,
// smem 112.4 KB -> 2 CTAs/SM.
// ---------------------------------------------------------------------------
#define RS2 132
#define SMEM_B_BYTES (28104 * 4)   // 112416 < 113664 -> 2 CTAs/SM

__global__ void __launch_bounds__(128, 2) steps_kernel(
    const float* __restrict__ freq, const float* __restrict__ pres,
    const float* __restrict__ rmask, const int* __restrict__ perm_idx,
    const float* __restrict__ W1,  const float* __restrict__ b1,
    const float* __restrict__ b2,
    const float* __restrict__ W3,  const float* __restrict__ b3,
    float* __restrict__ out)
{
  extern __shared__ float smf[];
  float* W2t  = smf;                 // [128][132] tf32 bits        16896
  float* h1   = W2t + 16896;         // [64][132] fp32               8448
  float* W1e  = h1 + 8448;           // [12][128]                    1536
  float* W3p  = W1e + 1536;          // [128][2]                      256
  float* b2s  = W3p + 256;           // [128]                         128
  float* st   = b2s + 128;           // [64][12]                      768
  int*   sridx= (int*)(st + 768);    // [64]                           64
  float* wred = (float*)(sridx+64);  // [8]                             8

  const int tid  = threadIdx.x;
  const int wid  = tid >> 5, lane = tid & 31;
  const int gr   = lane >> 2, tg = lane & 3;
  const int wm   = wid * 16;
  const int row0 = blockIdx.x * 64;

  // ---- smem init ----
  for (int i = tid; i < 4096; i += 128){          // W2t (pad 132)
    int n = i >> 5, c = (i & 31) * 4;
    *(float4*)&W2t[n*RS2 + c] = *(const float4*)&g_W2t[n*HH + c];
  }
  for (int i = tid; i < 384; i += 128)            // W1e rows 1024..1035
    *(float4*)&W1e[i*4] = *(const float4*)&W1[1024*HH + i*4];
  for (int i = tid; i < 64; i += 128)             // W3 [128][2]
    *(float4*)&W3p[i*4] = *(const float4*)&W3[i*4];
  if (tid < 128) b2s[tid] = b2[tid];
  for (int i = tid; i < 768; i += 128) st[i] = 0.f;
  __syncthreads();

  // ---- base = Y0 + b1, thread owns rows wm..wm+15, cols lane*4..+3 ----
  const float4 b1v = *(const float4*)&b1[lane*4];
  float4 base[16];
#pragma unroll
  for (int r = 0; r < 16; r++){
    float4 y = *(const float4*)(g_Y0 + (size_t)(row0 + wm + r)*HH + lane*4);
    base[r].x = y.x + b1v.x; base[r].y = y.y + b1v.y;
    base[r].z = y.z + b1v.z; base[r].w = y.w + b1v.w;
  }
  const float b30 = b3[0], b31 = b3[1];

  int p_lo = 0, p_hi = 0;
  if (tg == 0){
    p_lo = perm_idx[row0 + wm + gr];
    p_hi = perm_idx[row0 + wm + gr + 8];
  }

  float lsum = 0.f, msum = 0.f;

  for (int step = 0; step < 3; step++){
    // (a) tail lanes publish ridx + fetch ground truth
    float gtf_lo=0, gtp_lo=0, m_lo=0, gtf_hi=0, gtp_hi=0, m_hi=0;
    int r_lo=0, r_hi=0;
    if (tg == 0){
      r_lo = c_perms[p_lo][step]; r_hi = c_perms[p_hi][step];
      sridx[wm+gr]   = r_lo;
      sridx[wm+gr+8] = r_hi;
      size_t qlo = (size_t)(row0+wm+gr)*3 + r_lo;
      size_t qhi = (size_t)(row0+wm+gr+8)*3 + r_hi;
      gtf_lo = freq[qlo]; gtp_lo = pres[qlo]; m_lo = rmask[qlo];
      gtf_hi = freq[qhi]; gtp_hi = pres[qhi]; m_hi = rmask[qhi];
    }
    __syncthreads();

    // (b) layer 1 -> h1 smem
#pragma unroll
    for (int r = 0; r < 16; r++){
      float4 acc = base[r];
      int ri = sridx[wm+r];
      if (step > 0){
#pragma unroll
        for (int i = 0; i < 9; i++){
          float s = st[(wm+r)*12 + i];
          float4 w = *(float4*)&W1e[i*HH + lane*4];
          acc.x = fmaf(s, w.x, acc.x); acc.y = fmaf(s, w.y, acc.y);
          acc.z = fmaf(s, w.z, acc.z); acc.w = fmaf(s, w.w, acc.w);
        }
      }
      float4 w = *(float4*)&W1e[(9+ri)*HH + lane*4];
      acc.x = gelu_f(acc.x + w.x); acc.y = gelu_f(acc.y + w.y);
      acc.z = gelu_f(acc.z + w.z); acc.w = gelu_f(acc.w + w.w);
      *(float4*)&h1[(wm+r)*RS2 + lane*4] = acc;
    }
    __syncthreads();

    // (c) layer 2: warp tile 16x128 mma, K=128
    float acc[16][4];
#pragma unroll
    for (int nt = 0; nt < 16; nt++)
#pragma unroll
      for (int i = 0; i < 4; i++) acc[nt][i] = 0.f;

#pragma unroll
    for (int kk = 0; kk < 16; kk++){
      const int kc = kk * 8;
      uint32_t af[4];
      af[0] = f2tf(h1[(wm+gr)*RS2   + kc + tg]);
      af[1] = f2tf(h1[(wm+gr+8)*RS2 + kc + tg]);
      af[2] = f2tf(h1[(wm+gr)*RS2   + kc + tg + 4]);
      af[3] = f2tf(h1[(wm+gr+8)*RS2 + kc + tg + 4]);
#pragma unroll
      for (int nt = 0; nt < 16; nt++){
        uint32_t bf[2];
        bf[0] = __float_as_uint(W2t[(nt*8+gr)*RS2 + kc + tg]);
        bf[1] = __float_as_uint(W2t[(nt*8+gr)*RS2 + kc + tg + 4]);
        mma_tf32(acc[nt], af, bf);
      }
    }

    // (d) gelu + W3 projection on fragments
    float pf_lo = 0.f, z_lo = 0.f, pf_hi = 0.f, z_hi = 0.f;
#pragma unroll
    for (int nt = 0; nt < 16; nt++){
      int c0 = nt*8 + 2*tg;
      float bb0 = b2s[c0], bb1 = b2s[c0+1];
      float g0 = gelu_f(acc[nt][0] + bb0);
      float g1 = gelu_f(acc[nt][1] + bb1);
      float g2 = gelu_f(acc[nt][2] + bb0);
      float g3 = gelu_f(acc[nt][3] + bb1);
      float2 wA = *(float2*)&W3p[c0*2];
      float2 wB = *(float2*)&W3p[(c0+1)*2];
      pf_lo = fmaf(g0, wA.x, fmaf(g1, wB.x, pf_lo));
      z_lo  = fmaf(g0, wA.y, fmaf(g1, wB.y, z_lo));
      pf_hi = fmaf(g2, wA.x, fmaf(g3, wB.x, pf_hi));
      z_hi  = fmaf(g2, wA.y, fmaf(g3, wB.y, z_hi));
    }
#pragma unroll
    for (int o = 1; o <= 2; o <<= 1){
      pf_lo += __shfl_xor_sync(0xffffffffu, pf_lo, o);
      z_lo  += __shfl_xor_sync(0xffffffffu, z_lo,  o);
      pf_hi += __shfl_xor_sync(0xffffffffu, pf_hi, o);
      z_hi  += __shfl_xor_sync(0xffffffffu, z_hi,  o);
    }

    // (e) per-row tail on tg==0 lanes (2 rows each)
    if (tg == 0){
#pragma unroll
      for (int hh = 0; hh < 2; hh++){
        int   row  = wm + gr + hh*8;
        float pf   = (hh ? pf_hi : pf_lo) + b30;
        float z    = (hh ? z_hi  : z_lo)  + b31;
        float gtf  = hh ? gtf_hi : gtf_lo;
        float gtp  = hh ? gtp_hi : gtp_lo;
        float m    = hh ? m_hi   : m_lo;
        int   ri   = hh ? r_hi   : r_lo;
        float d  = pf - gtf;
        float pl = (fmaxf(z, 0.f) - z*gtp + log1pf(expf(-fabsf(z)))) * m;
        lsum += d*d*m + pl;
        msum += m;
        float sig   = 1.f / (1.f + expf(-z));
        float act_f = (m > 0.5f) ? pf  : gtf;
        float act_p = (m > 0.5f) ? sig : gtp;
        st[row*12 + 3*ri + 0] = act_f;
        st[row*12 + 3*ri + 1] = act_p;
        st[row*12 + 3*ri + 2] = 1.f;
        size_t rowr = (size_t)(row0 + row);
        out[1 + rowr*3 + ri]                = act_f;
        out[1 + (size_t)3*NB + rowr*3 + ri] = act_p;
      }
    }
  }

  // block loss reduction (deterministic)
#pragma unroll
  for (int o = 16; o; o >>= 1){
    lsum += __shfl_xor_sync(0xffffffffu, lsum, o);
    msum += __shfl_xor_sync(0xffffffffu, msum, o);
  }
  if (lane == 0){ wred[wid*2] = lsum; wred[wid*2+1] = msum; }
  __syncthreads();
  if (tid == 0){
    float L = 0.f, M = 0.f;
#pragma unroll
    for (int w = 0; w < 4; w++){ L += wred[w*2]; M += wred[w*2+1]; }
    g_part[blockIdx.x*2]   = L;
    g_part[blockIdx.x*2+1] = M;
  }
}

// ---------------------------------------------------------------------------
// Kernel C: deterministic final reduction -> out[0]
// ---------------------------------------------------------------------------
__global__ void __launch_bounds__(256) finalize_kernel(float* __restrict__ out)
{
  __shared__ float sL[256], sM[256];
  int tid = threadIdx.x;
  float L = 0.f, M = 0.f;
  for (int i = tid; i < 2048; i += 256){ L += g_part[2*i]; M += g_part[2*i+1]; }
  sL[tid] = L; sM[tid] = M;
  __syncthreads();
  for (int s = 128; s; s >>= 1){
    if (tid < s){ sL[tid] += sL[tid+s]; sM[tid] += sM[tid+s]; }
    __syncthreads();
  }
  if (tid == 0) out[0] = sL[0] / (sM[0] + 1e-8f);
}

// ---------------------------------------------------------------------------
extern "C" void kernel_launch(void* const* d_in, const int* in_sizes, int n_in,
                              void* d_out, int out_size)
{
  const float* seq   = (const float*)d_in[0];
  const float* freq  = (const float*)d_in[1];
  const float* pres  = (const float*)d_in[2];
  const float* rmask = (const float*)d_in[3];
  const int*   perm  = (const int*)  d_in[4];
  const float* W1    = (const float*)d_in[5];
  const float* b1    = (const float*)d_in[6];
  const float* W2    = (const float*)d_in[7];
  const float* b2    = (const float*)d_in[8];
  const float* W3    = (const float*)d_in[9];
  const float* b3    = (const float*)d_in[10];
  float* out = (float*)d_out;

  cudaFuncSetAttribute(tc_gemm,
                       cudaFuncAttributeMaxDynamicSharedMemorySize, SMEM_G_BYTES);
  cudaFuncSetAttribute(steps_kernel,
                       cudaFuncAttributeMaxDynamicSharedMemorySize, SMEM_B_BYTES);

  prep_weights<<<576, 256>>>(W1, W2);
  tc_gemm<<<NB/128, 128, SMEM_G_BYTES>>>(seq);
  steps_kernel<<<NB/64, 128, SMEM_B_BYTES>>>(freq, pres, rmask, perm,
                                             W1, b1, b2, W3, b3, out);
  finalize_kernel<<<1, 256>>>(out);
}

// round 16
// speedup vs baseline: 1.6484x; 1.3404x over previous
#include <cuda_runtime.h>
#include <cuda_fp16.h>
#include <math.h>
#include <stdint.h>

#define NB 131072
#define DD 1024
#define HH 128

// Scratch (allocation-free rule: __device__ globals)
__device__ float    g_Y0[(size_t)NB * HH];   // 67 MB: seq_embed @ W1[:1024]
__device__ uint32_t g_W1h[HH * (DD/2)];      // W1[:1024]^T fp16 k-pairs [n][kp<512]
__device__ uint32_t g_W2h[HH * (HH/2)];      // W2^T fp16 k-pairs [n][kp<64]
__device__ float    g_part[2048 * 2];        // per-block (loss_sum, n_masked)

__constant__ int c_perms[6][3] = {
  {0,1,2},{0,2,1},{1,0,2},{1,2,0},{2,0,1},{2,1,0}
};

// Fast gelu (R14 proven): A&S 7.1.26 erf, |abs err| <= 1.5e-7.
__device__ __forceinline__ float gelu_f(float x){
  float az = fabsf(x) * 0.7071067811865476f;
  float d  = fmaf(0.3275911f, az, 1.0f);
  float t;
  asm("rcp.approx.f32 %0, %1;" : "=f"(t) : "f"(d));
  float y = t * fmaf(t, fmaf(t, fmaf(t, fmaf(t, 1.061405429f, -1.453152027f),
                                     1.421413741f), -0.284496736f), 0.254829592f);
  float e = __expf(-az * az);
  float erfv = fmaf(-y, e, 1.0f);
  float s = copysignf(erfv, x);
  return 0.5f * x * (1.0f + s);
}

// ---------------------------------------------------------------------------
// PTX helpers (baseline sm_100: cp.async + mma.sync fp16 m16n8k16)
// ---------------------------------------------------------------------------
__device__ __forceinline__ void cp_async16(uint32_t dst, const void* src){
  asm volatile("cp.async.cg.shared.global [%0], [%1], 16;" :: "r"(dst), "l"(src) : "memory");
}
__device__ __forceinline__ void cp_commit(){
  asm volatile("cp.async.commit_group;" ::: "memory");
}
__device__ __forceinline__ uint32_t smem_u32(const void* p){
  uint32_t a;
  asm("{ .reg .u64 t; cvta.to.shared.u64 t, %1; cvt.u32.u64 %0, t; }" : "=r"(a) : "l"(p));
  return a;
}
__device__ __forceinline__ uint32_t pack_h2(float lo, float hi){
  __half2 h = __floats2half2_rn(lo, hi);       // .x = lo (low 16 bits)
  return *reinterpret_cast<uint32_t*>(&h);
}
__device__ __forceinline__ void mma_f16(float* c, const uint32_t* a,
                                        uint32_t b0, uint32_t b1){
  asm volatile(
    "mma.sync.aligned.m16n8k16.row.col.f32.f16.f16.f32 "
    "{%0,%1,%2,%3}, {%4,%5,%6,%7}, {%8,%9}, {%0,%1,%2,%3};"
    : "+f"(c[0]), "+f"(c[1]), "+f"(c[2]), "+f"(c[3])
    : "r"(a[0]), "r"(a[1]), "r"(a[2]), "r"(a[3]), "r"(b0), "r"(b1));
}

// ---------------------------------------------------------------------------
// Kernel T: W1[:1024]^T, W2^T -> fp16 k-paired uint32 arrays
// ---------------------------------------------------------------------------
__global__ void __launch_bounds__(256) prep_weights(
    const float* __restrict__ W1, const float* __restrict__ W2)
{
  int i = blockIdx.x * 256 + threadIdx.x;          // 0 .. 73727
  if (i < 65536){
    int n = i >> 9, kp = i & 511;
    float w0 = W1[(size_t)(2*kp)   * HH + n];
    float w1 = W1[(size_t)(2*kp+1) * HH + n];
    g_W1h[n*512 + kp] = pack_h2(w0, w1);
  } else if (i < 73728){
    int j = i - 65536;                             // 0 .. 8191
    int n = j >> 6, kp = j & 63;
    float w0 = W2[(2*kp)   * HH + n];
    float w1 = W2[(2*kp+1) * HH + n];
    g_W2h[n*64 + kp] = pack_h2(w0, w1);
  }
}

// ---------------------------------------------------------------------------
// Kernel A: fp16 m16n8k16 GEMM: Y0 = seq_embed[B,1024] @ W1[:1024,:128]
// CTA 128x128, 4 warps (2x2), warp tile 64x64, K chunk 32, 3-stage cp.async.
// A staged fp32 (stride 40: conflict-free LDS.64), B staged fp16-paired
// (stride 20 uints: conflict-free LDS.32).
// ---------------------------------------------------------------------------
#define RSA 40
#define RSB 20
#define A_STG_F (128 * RSA)       // 5120 floats
#define B_STG_U (128 * RSB)       // 2560 uints
#define SMEM_G_BYTES ((3*A_STG_F + 3*B_STG_U) * 4)   // 92160 -> 2 CTAs/SM

__global__ void __launch_bounds__(128, 2) tc_gemm(const float* __restrict__ A)
{
  extern __shared__ float sm[];
  uint32_t* smu = (uint32_t*)(sm + 3*A_STG_F);
  const uint32_t sbase = smem_u32(sm);
  const uint32_t bbase = sbase + (uint32_t)(3*A_STG_F) * 4u;
  const int tid  = threadIdx.x;
  const int wid  = tid >> 5, lane = tid & 31;
  const int gr   = lane >> 2, tg = lane & 3;
  const int m0   = blockIdx.x * 128;
  const int wm   = (wid & 1) * 64;
  const int wn   = (wid >> 1) * 64;

  const float* Abase = A + (size_t)m0 * DD;

  auto load_stage = [&](int s){
    const int buf = s % 3;
    const int k0  = s * 32;
    const uint32_t aB = sbase + (uint32_t)(buf * A_STG_F) * 4u;
    const uint32_t bB = bbase + (uint32_t)(buf * B_STG_U) * 4u;
#pragma unroll
    for (int j = 0; j < 8; j++){                 // A: 128 rows x 8 x 16B
      int idx = tid + 128*j;
      int row = idx >> 3, cc = idx & 7;
      cp_async16(aB + (uint32_t)(row*RSA + cc*4)*4u,
                 Abase + (size_t)row*DD + k0 + cc*4);
    }
#pragma unroll
    for (int j = 0; j < 4; j++){                 // B: 128 rows x 4 x 16B (fp16)
      int idx = tid + 128*j;
      int row = idx >> 2, cc = idx & 3;
      cp_async16(bB + (uint32_t)(row*RSB + cc*4)*4u,
                 g_W1h + row*512 + (k0 >> 1) + cc*4);
    }
    cp_commit();
  };

  float acc[4][8][4];
#pragma unroll
  for (int mt = 0; mt < 4; mt++)
#pragma unroll
    for (int nt = 0; nt < 8; nt++)
#pragma unroll
      for (int i = 0; i < 4; i++) acc[mt][nt][i] = 0.f;

  load_stage(0);
  load_stage(1);

  for (int s = 0; s < 32; s++){
    if (s < 31) asm volatile("cp.async.wait_group 1;" ::: "memory");
    else        asm volatile("cp.async.wait_group 0;" ::: "memory");
    __syncthreads();
    if (s + 2 < 32) load_stage(s + 2);

    const float*    Abuf = sm  + (s % 3) * A_STG_F;
    const uint32_t* Bbuf = smu + (s % 3) * B_STG_U;

#pragma unroll
    for (int c = 0; c < 2; c++){                 // two k16 chunks per stage
      const int kc = c * 16;
      uint32_t af[4][4], bf[8][2];
#pragma unroll
      for (int mt = 0; mt < 4; mt++){
        int r = wm + mt*16 + gr;
        float2 v0 = *(const float2*)&Abuf[r*RSA     + kc + 2*tg];
        float2 v1 = *(const float2*)&Abuf[(r+8)*RSA + kc + 2*tg];
        float2 v2 = *(const float2*)&Abuf[r*RSA     + kc + 2*tg + 8];
        float2 v3 = *(const float2*)&Abuf[(r+8)*RSA + kc + 2*tg + 8];
        af[mt][0] = pack_h2(v0.x, v0.y);
        af[mt][1] = pack_h2(v1.x, v1.y);
        af[mt][2] = pack_h2(v2.x, v2.y);
        af[mt][3] = pack_h2(v3.x, v3.y);
      }
#pragma unroll
      for (int nt = 0; nt < 8; nt++){
        int n = wn + nt*8 + gr;
        bf[nt][0] = Bbuf[n*RSB + c*8 + tg];
        bf[nt][1] = Bbuf[n*RSB + c*8 + tg + 4];
      }
#pragma unroll
      for (int mt = 0; mt < 4; mt++)
#pragma unroll
        for (int nt = 0; nt < 8; nt++)
          mma_f16(acc[mt][nt], af[mt], bf[nt][0], bf[nt][1]);
    }
  }

  // epilogue (C frag layout identical to m16n8 tf32)
#pragma unroll
  for (int mt = 0; mt < 4; mt++){
#pragma unroll
    for (int nt = 0; nt < 8; nt++){
      int row = m0 + wm + mt*16 + gr;
      int col = wn + nt*8 + 2*tg;
      float2 lo = { acc[mt][nt][0], acc[mt][nt][1] };
      float2 hi = { acc[mt][nt][2], acc[mt][nt][3] };
      *(float2*)&g_Y0[(size_t)row*HH + col]     = lo;
      *(float2*)&g_Y0[(size_t)(row+8)*HH + col] = hi;
    }
  }
}

// ---------------------------------------------------------------------------
// Kernel B: fused 3-step decoder, layer-2 on fp16 mma.
// CTA = 64 rows, 128 threads (4 warps). smem 63.3 KB -> 2 CTAs/SM.
// FIXED vs R15: fp16-pair rows are 64 uints, strides RSH/RSW = 68 (was 36/44
// -> buffer overflow -> NaN).
// ---------------------------------------------------------------------------
#define RSH 68   // h1h row stride (uints): 64 pairs + 4 pad
#define RSW 68   // W2hs row stride (uints)
#define SMEM_B_BYTES (15816 * 4)   // 63264

__global__ void __launch_bounds__(128, 2) steps_kernel(
    const float* __restrict__ freq, const float* __restrict__ pres,
    const float* __restrict__ rmask, const int* __restrict__ perm_idx,
    const float* __restrict__ W1,  const float* __restrict__ b1,
    const float* __restrict__ b2,
    const float* __restrict__ W3,  const float* __restrict__ b3,
    float* __restrict__ out)
{
  extern __shared__ float smf[];
  uint32_t* W2hs = (uint32_t*)smf;            // [128][68]   8704 words
  uint32_t* h1h  = W2hs + 128*RSW;            // [64][68]    4352
  float* W1e  = (float*)(h1h + 64*RSH);       // [12][128]   1536
  float* W3p  = W1e + 1536;                   // [128][2]     256
  float* b2s  = W3p + 256;                    // [128]        128
  float* st   = b2s + 128;                    // [64][12]     768
  int*   sridx= (int*)(st + 768);             // [64]          64
  float* wred = (float*)(sridx + 64);         // [8]            8

  const int tid  = threadIdx.x;
  const int wid  = tid >> 5, lane = tid & 31;
  const int gr   = lane >> 2, tg = lane & 3;
  const int wm   = wid * 16;
  const int row0 = blockIdx.x * 64;

  // ---- smem init ----
  for (int i = tid; i < 2048; i += 128){           // W2hs: 128 rows x 16 uint4
    int n = i >> 4, c4 = i & 15;
    *(uint4*)&W2hs[n*RSW + c4*4] = *(const uint4*)&g_W2h[n*64 + c4*4];
  }
  for (int i = tid; i < 384; i += 128)             // W1e rows 1024..1035
    *(float4*)&W1e[i*4] = *(const float4*)&W1[1024*HH + i*4];
  for (int i = tid; i < 64; i += 128)              // W3 [128][2]
    *(float4*)&W3p[i*4] = *(const float4*)&W3[i*4];
  if (tid < 128) b2s[tid] = b2[tid];
  for (int i = tid; i < 768; i += 128) st[i] = 0.f;
  __syncthreads();

  // ---- base = Y0 + b1 (registers) ----
  const float4 b1v = *(const float4*)&b1[lane*4];
  float4 base[16];
#pragma unroll
  for (int r = 0; r < 16; r++){
    float4 y = *(const float4*)(g_Y0 + (size_t)(row0 + wm + r)*HH + lane*4);
    base[r].x = y.x + b1v.x; base[r].y = y.y + b1v.y;
    base[r].z = y.z + b1v.z; base[r].w = y.w + b1v.w;
  }
  const float b30 = b3[0], b31 = b3[1];

  int p_lo = 0, p_hi = 0;
  if (tg == 0){
    p_lo = perm_idx[row0 + wm + gr];
    p_hi = perm_idx[row0 + wm + gr + 8];
  }

  float lsum = 0.f, msum = 0.f;

  for (int step = 0; step < 3; step++){
    // (a) tail lanes publish ridx + fetch ground truth
    float gtf_lo=0, gtp_lo=0, m_lo=0, gtf_hi=0, gtp_hi=0, m_hi=0;
    int r_lo=0, r_hi=0;
    if (tg == 0){
      r_lo = c_perms[p_lo][step]; r_hi = c_perms[p_hi][step];
      sridx[wm+gr]   = r_lo;
      sridx[wm+gr+8] = r_hi;
      size_t qlo = (size_t)(row0+wm+gr)*3 + r_lo;
      size_t qhi = (size_t)(row0+wm+gr+8)*3 + r_hi;
      gtf_lo = freq[qlo]; gtp_lo = pres[qlo]; m_lo = rmask[qlo];
      gtf_hi = freq[qhi]; gtp_hi = pres[qhi]; m_hi = rmask[qhi];
    }
    __syncthreads();

    // (b) layer 1 -> h1 (fp16-paired smem)
#pragma unroll
    for (int r = 0; r < 16; r++){
      float4 acc = base[r];
      int ri = sridx[wm+r];
      if (step > 0){
#pragma unroll
        for (int i = 0; i < 9; i++){
          float s = st[(wm+r)*12 + i];
          float4 w = *(float4*)&W1e[i*HH + lane*4];
          acc.x = fmaf(s, w.x, acc.x); acc.y = fmaf(s, w.y, acc.y);
          acc.z = fmaf(s, w.z, acc.z); acc.w = fmaf(s, w.w, acc.w);
        }
      }
      float4 w = *(float4*)&W1e[(9+ri)*HH + lane*4];
      acc.x = gelu_f(acc.x + w.x); acc.y = gelu_f(acc.y + w.y);
      acc.z = gelu_f(acc.z + w.z); acc.w = gelu_f(acc.w + w.w);
      uint2 uu = { pack_h2(acc.x, acc.y), pack_h2(acc.z, acc.w) };
      *(uint2*)&h1h[(wm+r)*RSH + lane*2] = uu;
    }
    __syncthreads();

    // (c) layer 2: warp tile 16x128, K=128 via 8 x k16 fp16 mma
    float acc[16][4];
#pragma unroll
    for (int nt = 0; nt < 16; nt++)
#pragma unroll
      for (int i = 0; i < 4; i++) acc[nt][i] = 0.f;

#pragma unroll
    for (int c = 0; c < 8; c++){
      uint32_t af[4];
      int rb = (wm+gr)*RSH + c*8 + tg;
      af[0] = h1h[rb];
      af[1] = h1h[rb + 8*RSH];
      af[2] = h1h[rb + 4];
      af[3] = h1h[rb + 8*RSH + 4];
#pragma unroll
      for (int nt = 0; nt < 16; nt++){
        int n = nt*8 + gr;
        uint32_t b0 = W2hs[n*RSW + c*8 + tg];
        uint32_t b1r = W2hs[n*RSW + c*8 + tg + 4];
        mma_f16(acc[nt], af, b0, b1r);
      }
    }

    // (d) gelu + W3 projection on fragments (C layout unchanged)
    float pf_lo = 0.f, z_lo = 0.f, pf_hi = 0.f, z_hi = 0.f;
#pragma unroll
    for (int nt = 0; nt < 16; nt++){
      int c0 = nt*8 + 2*tg;
      float bb0 = b2s[c0], bb1 = b2s[c0+1];
      float g0 = gelu_f(acc[nt][0] + bb0);
      float g1 = gelu_f(acc[nt][1] + bb1);
      float g2 = gelu_f(acc[nt][2] + bb0);
      float g3 = gelu_f(acc[nt][3] + bb1);
      float2 wA = *(float2*)&W3p[c0*2];
      float2 wB = *(float2*)&W3p[(c0+1)*2];
      pf_lo = fmaf(g0, wA.x, fmaf(g1, wB.x, pf_lo));
      z_lo  = fmaf(g0, wA.y, fmaf(g1, wB.y, z_lo));
      pf_hi = fmaf(g2, wA.x, fmaf(g3, wB.x, pf_hi));
      z_hi  = fmaf(g2, wA.y, fmaf(g3, wB.y, z_hi));
    }
#pragma unroll
    for (int o = 1; o <= 2; o <<= 1){
      pf_lo += __shfl_xor_sync(0xffffffffu, pf_lo, o);
      z_lo  += __shfl_xor_sync(0xffffffffu, z_lo,  o);
      pf_hi += __shfl_xor_sync(0xffffffffu, pf_hi, o);
      z_hi  += __shfl_xor_sync(0xffffffffu, z_hi,  o);
    }

    // (e) per-row tail on tg==0 lanes (2 rows each)
    if (tg == 0){
#pragma unroll
      for (int hh = 0; hh < 2; hh++){
        int   row  = wm + gr + hh*8;
        float pf   = (hh ? pf_hi : pf_lo) + b30;
        float z    = (hh ? z_hi  : z_lo)  + b31;
        float gtf  = hh ? gtf_hi : gtf_lo;
        float gtp  = hh ? gtp_hi : gtp_lo;
        float m    = hh ? m_hi   : m_lo;
        int   ri   = hh ? r_hi   : r_lo;
        float d  = pf - gtf;
        float pl = (fmaxf(z, 0.f) - z*gtp + log1pf(expf(-fabsf(z)))) * m;
        lsum += d*d*m + pl;
        msum += m;
        float sig   = 1.f / (1.f + expf(-z));
        float act_f = (m > 0.5f) ? pf  : gtf;
        float act_p = (m > 0.5f) ? sig : gtp;
        st[row*12 + 3*ri + 0] = act_f;
        st[row*12 + 3*ri + 1] = act_p;
        st[row*12 + 3*ri + 2] = 1.f;
        size_t rowr = (size_t)(row0 + row);
        out[1 + rowr*3 + ri]                = act_f;
        out[1 + (size_t)3*NB + rowr*3 + ri] = act_p;
      }
    }
  }

  // block loss reduction (deterministic)
#pragma unroll
  for (int o = 16; o; o >>= 1){
    lsum += __shfl_xor_sync(0xffffffffu, lsum, o);
    msum += __shfl_xor_sync(0xffffffffu, msum, o);
  }
  if (lane == 0){ wred[wid*2] = lsum; wred[wid*2+1] = msum; }
  __syncthreads();
  if (tid == 0){
    float L = 0.f, M = 0.f;
#pragma unroll
    for (int w = 0; w < 4; w++){ L += wred[w*2]; M += wred[w*2+1]; }
    g_part[blockIdx.x*2]   = L;
    g_part[blockIdx.x*2+1] = M;
  }
}

// ---------------------------------------------------------------------------
// Kernel C: deterministic final reduction -> out[0]
// ---------------------------------------------------------------------------
__global__ void __launch_bounds__(256) finalize_kernel(float* __restrict__ out)
{
  __shared__ float sL[256], sM[256];
  int tid = threadIdx.x;
  float L = 0.f, M = 0.f;
  for (int i = tid; i < 2048; i += 256){ L += g_part[2*i]; M += g_part[2*i+1]; }
  sL[tid] = L; sM[tid] = M;
  __syncthreads();
  for (int s = 128; s; s >>= 1){
    if (tid < s){ sL[tid] += sL[tid+s]; sM[tid] += sM[tid+s]; }
    __syncthreads();
  }
  if (tid == 0) out[0] = sL[0] / (sM[0] + 1e-8f);
}

// ---------------------------------------------------------------------------
extern "C" void kernel_launch(void* const* d_in, const int* in_sizes, int n_in,
                              void* d_out, int out_size)
{
  const float* seq   = (const float*)d_in[0];
  const float* freq  = (const float*)d_in[1];
  const float* pres  = (const float*)d_in[2];
  const float* rmask = (const float*)d_in[3];
  const int*   perm  = (const int*)  d_in[4];
  const float* W1    = (const float*)d_in[5];
  const float* b1    = (const float*)d_in[6];
  const float* W2    = (const float*)d_in[7];
  const float* b2    = (const float*)d_in[8];
  const float* W3    = (const float*)d_in[9];
  const float* b3    = (const float*)d_in[10];
  float* out = (float*)d_out;

  cudaFuncSetAttribute(tc_gemm,
                       cudaFuncAttributeMaxDynamicSharedMemorySize, SMEM_G_BYTES);
  cudaFuncSetAttribute(steps_kernel,
                       cudaFuncAttributeMaxDynamicSharedMemorySize, SMEM_B_BYTES);

  prep_weights<<<288, 256>>>(W1, W2);
  tc_gemm<<<NB/128, 128, SMEM_G_BYTES>>>(seq);
  steps_kernel<<<NB/64, 128, SMEM_B_BYTES>>>(freq, pres, rmask, perm,
                                             W1, b1, b2, W3, b3, out);
  finalize_kernel<<<1, 256>>>(out);
}